// round 10
// baseline (speedup 1.0000x reference)
#include <cuda_runtime.h>
#include <cstddef>
#include <cstdint>

#define NB 64
#define NT 1024
#define NV 256
#define NS 256
#define ND 24
#define NL 513          // 2*NS+1
#define DGA 1344        // allocated dg rows per batch
#define EMW 260         // em row: [0..255]=labels, [256]=blank, pad to 260
#define KPH 16          // steps per phase
#define MLAG_S 5        // sdtw inter-warp lag (phases)
#define NPH_S 83        // sdtw phases: 68 active + 5*3 lag
#define NPH_C 67        // ctc phases: 64 active + 3 lag
#define GAMMA 0.1f
#define NEGF (-1e10f)
#define BIGF (1e10f)

// Scratch (no allocation allowed)
__device__ float g_pred[NB * NT * ND];            // predicted features (B,T,D)
__device__ float g_cost[(size_t)NB * DGA * NS];   // cost, [b][dg][j], dg=i+j+2
__device__ float g_em[(size_t)NB * NT * EMW];     // emissions per label + blank
__device__ float g_loss[2 * NB];                  // [0..63] ctc, [64..127] sdtw

// mn <= md <= mx with pure min/max (no cancellation)
__device__ __forceinline__ void sort3(float a, float b, float c,
                                      float& mn, float& md, float& mx) {
    float t1 = fminf(a, b);
    float t2 = fmaxf(a, b);
    mn = fminf(t1, c);
    mx = fmaxf(t2, c);
    md = fmaxf(t1, fminf(t2, c));
}

__device__ __forceinline__ void cpAsync16(uint32_t dst, const void* src) {
    asm volatile("cp.async.cg.shared.global [%0], [%1], 16;" :: "r"(dst), "l"(src));
}
__device__ __forceinline__ void cpAsync4(uint32_t dst, const void* src) {
    asm volatile("cp.async.ca.shared.global [%0], [%1], 4;" :: "r"(dst), "l"(src));
}
__device__ __forceinline__ void cpCommit() {
    asm volatile("cp.async.commit_group;" ::: "memory");
}
__device__ __forceinline__ void cpWait2() {
    asm volatile("cp.async.wait_group 2;" ::: "memory");
}

// ----------------------------------------------------------------------------
// Kernel 1: pred = exp(log_probs) @ fm   (65536 x 256) @ (256 x 24)
// ----------------------------------------------------------------------------
__global__ __launch_bounds__(256) void prep_kernel(const float* __restrict__ lp,
                                                   const float* __restrict__ fm) {
    __shared__ float eS[64 * 129];
    __shared__ float fmS[64 * 25];

    const int tid = threadIdx.x;
    const int row0 = blockIdx.x * 128;
    const int rg = tid >> 3;
    const int dgrp = tid & 7;

    float acc[4][3];
#pragma unroll
    for (int i = 0; i < 4; i++)
#pragma unroll
        for (int j = 0; j < 3; j++) acc[i][j] = 0.f;

    for (int v0 = 0; v0 < NV; v0 += 64) {
        for (int idx = tid; idx < 64 * 24; idx += 256) {
            int v = idx / 24, d = idx - v * 24;
            fmS[v * 25 + d] = fm[(v0 + v) * ND + d];
        }
        for (int idx = tid; idx < 128 * 64; idx += 256) {
            int r = idx >> 6, v = idx & 63;
            eS[v * 129 + r] = __expf(lp[(size_t)(row0 + r) * NV + v0 + v]);
        }
        __syncthreads();

#pragma unroll 4
        for (int v = 0; v < 64; v++) {
            float e0 = eS[v * 129 + rg * 4 + 0];
            float e1 = eS[v * 129 + rg * 4 + 1];
            float e2 = eS[v * 129 + rg * 4 + 2];
            float e3 = eS[v * 129 + rg * 4 + 3];
            float f0 = fmS[v * 25 + dgrp * 3 + 0];
            float f1 = fmS[v * 25 + dgrp * 3 + 1];
            float f2 = fmS[v * 25 + dgrp * 3 + 2];
            acc[0][0] += e0 * f0; acc[0][1] += e0 * f1; acc[0][2] += e0 * f2;
            acc[1][0] += e1 * f0; acc[1][1] += e1 * f1; acc[1][2] += e1 * f2;
            acc[2][0] += e2 * f0; acc[2][1] += e2 * f1; acc[2][2] += e2 * f2;
            acc[3][0] += e3 * f0; acc[3][1] += e3 * f1; acc[3][2] += e3 * f2;
        }
        __syncthreads();
    }

#pragma unroll
    for (int i = 0; i < 4; i++)
#pragma unroll
        for (int j = 0; j < 3; j++)
            g_pred[(size_t)(row0 + rg * 4 + i) * ND + dgrp * 3 + j] = acc[i][j];
}

// ----------------------------------------------------------------------------
// Kernel 2: sdtw cost matrix, layout [b][dg][j], coalesced via diagonal rotation.
// ----------------------------------------------------------------------------
__global__ __launch_bounds__(256) void cost_kernel(const float* __restrict__ fm,
                                                   const int* __restrict__ targets) {
    __shared__ float predS[64 * 25];
    __shared__ float qS[256 * 25];
    __shared__ float pn[64];
    __shared__ float qn[256];
    __shared__ int qlab[256];

    const int tid = threadIdx.x;
    const int b = blockIdx.y;
    const int i0 = blockIdx.x * 64;

    qlab[tid] = targets[b * NS + tid];
    for (int idx = tid; idx < 64 * 24; idx += 256)
        predS[(idx / 24) * 25 + (idx % 24)] = g_pred[(size_t)(b * NT + i0) * ND + idx];
    __syncthreads();
    for (int idx = tid; idx < 256 * 24; idx += 256) {
        int c = idx / 24, d = idx - c * 24;
        qS[c * 25 + d] = fm[qlab[c] * ND + d];
    }
    __syncthreads();
    if (tid < 64) {
        float s = 0.f;
#pragma unroll
        for (int d = 0; d < ND; d++) { float x = predS[tid * 25 + d]; s += x * x; }
        pn[tid] = s;
    }
    {
        float s = 0.f;
#pragma unroll
        for (int d = 0; d < ND; d++) { float x = qS[tid * 25 + d]; s += x * x; }
        qn[tid] = s;
    }
    __syncthreads();

    const int w = tid >> 5;
    const int lane = tid & 31;
    const int j0 = w * 32;

    float p0[ND], p1[ND];
#pragma unroll
    for (int k = 0; k < ND; k++) {
        p0[k] = predS[lane * 25 + k];
        p1[k] = predS[(lane + 32) * 25 + k];
    }
    const float pn0 = pn[lane], pn1 = pn[lane + 32];
    const size_t cb = (size_t)b * DGA;
    const int D0 = i0 + j0 + 2;

#pragma unroll 4
    for (int c = 0; c < 32; c++) {
        int jc = j0 + ((c - lane) & 31);
        float dot0 = 0.f, dot1 = 0.f;
#pragma unroll
        for (int k = 0; k < ND; k++) {
            float q = qS[jc * 25 + k];
            dot0 += p0[k] * q;
            dot1 += p1[k] * q;
        }
        float qnj = qn[jc];
        int dg0 = D0 + c + ((lane > c) ? 32 : 0);
        g_cost[(cb + dg0) * NS + jc] = pn0 + qnj - 2.f * dot0;
        g_cost[(cb + dg0 + 32) * NS + jc] = pn1 + qnj - 2.f * dot1;
    }
}

// ----------------------------------------------------------------------------
// Kernel 3: emission table em[b][t][j] = lp[t][tgt[j]] (j<256); [256] = blank.
// ----------------------------------------------------------------------------
__global__ __launch_bounds__(256) void em_kernel(const float* __restrict__ lp,
                                                 const int* __restrict__ targets) {
    __shared__ float rowS[4][256];
    __shared__ int tgtS[256];

    const int tid = threadIdx.x;
    const int b = blockIdx.x >> 4;
    const int t0 = (blockIdx.x & 15) << 6;

    tgtS[tid] = targets[b * NS + tid];
    const float* lpb = lp + ((size_t)b * NT + t0) * NV;
    float* emb = g_em + ((size_t)b * NT + t0) * EMW;
    __syncthreads();

    for (int tt = 0; tt < 64; tt += 4) {
#pragma unroll
        for (int r = 0; r < 4; r++)
            rowS[r][tid] = lpb[(size_t)(tt + r) * NV + tid];
        __syncthreads();
#pragma unroll
        for (int r = 0; r < 4; r++)
            emb[(size_t)(tt + r) * EMW + tid] = rowS[r][tgtS[tid]];
        if (tid < 4) emb[(size_t)(tt + tid) * EMW + 256] = rowS[tid][0];
        __syncthreads();
    }
}

// ----------------------------------------------------------------------------
// Kernel 4 (fused DP, 2 batches per block — dual independent chains per warp
// hide each other's dependency latency; cp.async staging; phase-skewed barriers):
//   blocks 0..31  -> soft-DTW for batches (2bid, 2bid+1)
//   blocks 32..63 -> CTC       for batches (2(bid-32), 2(bid-32)+1)
// ----------------------------------------------------------------------------
#define STROW 68        // staged row: 64 data floats (+blank at [64] for ctc)
#define STQ (3 * KPH * STROW)        // per (q,w) stage: 3 bufs
#define STAGE_FLOATS (8 * STQ)       // [q(2)][w(4)] -> 26112 floats
extern __shared__ float smf[];

__global__ __launch_bounds__(128) void main_kernel(const int* __restrict__ targets,
                                                   const int* __restrict__ in_len,
                                                   const int* __restrict__ tg_len) {
    float* stage = smf;                                  // [2][4][3][KPH][STROW]
    const int tid = threadIdx.x;                         // 0..127
    const int lane = tid & 31;
    const int w = tid >> 5;                              // 0..3
    const int bid = blockIdx.x;

    const uint32_t stBaseAddr = (uint32_t)__cvta_generic_to_shared(stage);
    const uint32_t stU0 = stBaseAddr + (uint32_t)((0 * 4 + w) * STQ) * 4u;
    const uint32_t stU1 = stBaseAddr + (uint32_t)((1 * 4 + w) * STQ) * 4u;
    const int rsel = lane >> 4;            // row parity this lane copies
    const int csel = lane & 15;            // 16B chunk within row

    if (bid < NB / 2) {
        // ======================= soft-DTW (2 batches) =======================
        float* bndR = smf + STAGE_FLOATS;                // [2][4][1312]
        const int b0 = 2 * bid, b1 = 2 * bid + 1;
        const int s0 = 64 * w + 2;
        const int jj0 = 2 * tid + 1;
        const int wp = (w == 0) ? 0 : (w - 1);

        for (int idx = tid; idx < 2 * 4 * 1312; idx += 128) bndR[idx] = BIGF;

        auto stageS = [&](int buf, int dgStart) {
#pragma unroll
            for (int r = 0; r < KPH / 2; r++) {
                int row = 2 * r + rsel;
                int dgr = dgStart + row;
                dgr = (dgr < 0) ? 0 : ((dgr > DGA - 1) ? DGA - 1 : dgr);
                uint32_t off = (uint32_t)((buf * KPH + row) * STROW + csel * 4) * 4u;
                cpAsync16(stU0 + off,
                          g_cost + ((size_t)b0 * DGA + dgr) * NS + 64 * w + csel * 4);
                cpAsync16(stU1 + off,
                          g_cost + ((size_t)b1 * DGA + dgr) * NS + 64 * w + csel * 4);
            }
            cpCommit();
        };

        stageS(0, s0 + (0 - MLAG_S * w) * KPH);
        stageS(1, s0 + (1 - MLAG_S * w) * KPH);
        __syncthreads();

        float Ra0 = BIGF, Ra1 = BIGF, r3a0, r3a1 = BIGF;   // batch 0
        float Rb0 = BIGF, Rb1 = BIGF, r3b0, r3b1 = BIGF;   // batch 1
        r3a0 = (tid == 0) ? 0.f : BIGF;
        r3b0 = (tid == 0) ? 0.f : BIGF;

        int buf = 0;
        for (int p = 0; p < NPH_S; p++) {
            int bufN = buf + 2; if (bufN >= 3) bufN -= 3;
            stageS(bufN, s0 + (p + 2 - MLAG_S * w) * KPH);
            cpWait2();
            __syncwarp();
            const int prel = p - MLAG_S * w;
            if (prel >= 0 && prel <= 67) {
                const int stB = prel * KPH;
                const float* rowA = stage + (0 * 4 + w) * STQ + buf * KPH * STROW + 2 * lane;
                const float* rowB = stage + (1 * 4 + w) * STQ + buf * KPH * STROW + 2 * lane;
#pragma unroll
                for (int k = 0; k < KPH; k++) {
                    const int dg = s0 + stB + k;
                    float2 ca = *(const float2*)(rowA + k * STROW);
                    float2 cb = *(const float2*)(rowB + k * STROW);
                    float r2a = __shfl_up_sync(0xffffffffu, Ra1, 1);
                    float r2b = __shfl_up_sync(0xffffffffu, Rb1, 1);
                    float bda = bndR[(0 * 4 + wp) * 1312 + dg - 1];
                    float bdb = bndR[(1 * 4 + wp) * 1312 + dg - 1];
                    r2a = (lane == 0) ? ((w == 0) ? BIGF : bda) : r2a;
                    r2b = (lane == 0) ? ((w == 0) ? BIGF : bdb) : r2b;
                    const int i0 = dg - jj0;
                    const bool v0 = (i0 >= 1 && i0 <= NT);
                    const bool v1 = (i0 - 1 >= 1 && i0 - 1 <= NT);
                    float mn, md, mx;
                    // batch0 cell0
                    sort3(Ra0, r2a, r3a0, mn, md, mx);
                    float sa0 = 1.f + __expf((mn - md) * 10.f) + __expf((mn - mx) * 10.f);
                    float Na0 = v0 ? (ca.x + mn - GAMMA * __logf(sa0)) : BIGF;
                    // batch1 cell0
                    sort3(Rb0, r2b, r3b0, mn, md, mx);
                    float sb0 = 1.f + __expf((mn - md) * 10.f) + __expf((mn - mx) * 10.f);
                    float Nb0 = v0 ? (cb.x + mn - GAMMA * __logf(sb0)) : BIGF;
                    // batch0 cell1
                    sort3(Ra1, Ra0, r3a1, mn, md, mx);
                    float sa1 = 1.f + __expf((mn - md) * 10.f) + __expf((mn - mx) * 10.f);
                    float Na1 = v1 ? (ca.y + mn - GAMMA * __logf(sa1)) : BIGF;
                    // batch1 cell1
                    sort3(Rb1, Rb0, r3b1, mn, md, mx);
                    float sb1 = 1.f + __expf((mn - md) * 10.f) + __expf((mn - mx) * 10.f);
                    float Nb1 = v1 ? (cb.y + mn - GAMMA * __logf(sb1)) : BIGF;
                    if (lane == 31) {
                        bndR[(0 * 4 + w) * 1312 + dg] = Na1;
                        bndR[(1 * 4 + w) * 1312 + dg] = Nb1;
                    }
                    if (dg == NT + NS && tid == 127) {
                        g_loss[NB + b0] = Na1;
                        g_loss[NB + b1] = Nb1;
                    }
                    r3a0 = r2a; r3a1 = Ra0; Ra0 = Na0; Ra1 = Na1;
                    r3b0 = r2b; r3b1 = Rb0; Rb0 = Nb0; Rb1 = Nb1;
                }
            }
            buf++; if (buf >= 3) buf -= 3;
            __syncthreads();
        }
    } else {
        // ======================= CTC forward (2 batches) =======================
        float* ringT = smf + STAGE_FLOATS;               // [2][4][32]
        float* actc = ringT + 2 * 4 * 32;                // [2][513]
        const int b0 = 2 * (bid - NB / 2), b1 = b0 + 1;
        const int wp = (w == 0) ? 0 : (w - 1);

        bool s1a = false, s3a, s1b = false, s3b;
        {
            int a2k = targets[b0 * NS + 2 * tid];
            int a2k1 = targets[b0 * NS + 2 * tid + 1];
            s3a = (a2k1 != a2k);
            if (tid > 0) s1a = (a2k != targets[b0 * NS + 2 * tid - 1]);
            int c2k = targets[b1 * NS + 2 * tid];
            int c2k1 = targets[b1 * NS + 2 * tid + 1];
            s3b = (c2k1 != c2k);
            if (tid > 0) s1b = (c2k != targets[b1 * NS + 2 * tid - 1]);
        }
        const float* emA = g_em + (size_t)b0 * NT * EMW;
        const float* emB = g_em + (size_t)b1 * NT * EMW;
        const int lenA = in_len[b0], lenB = in_len[b1];
        const int lenMax = (lenA > lenB) ? lenA : lenB;

        auto stageC = [&](int buf, int tStart) {
#pragma unroll
            for (int r = 0; r < KPH / 2; r++) {
                int row = 2 * r + rsel;
                int tr = tStart + row;
                tr = (tr < 0) ? 0 : ((tr > NT - 1) ? NT - 1 : tr);
                uint32_t off = (uint32_t)((buf * KPH + row) * STROW + csel * 4) * 4u;
                cpAsync16(stU0 + off, emA + (size_t)tr * EMW + 64 * w + csel * 4);
                cpAsync16(stU1 + off, emB + (size_t)tr * EMW + 64 * w + csel * 4);
            }
            if (lane < KPH) {
                int tr = tStart + lane;
                tr = (tr < 0) ? 0 : ((tr > NT - 1) ? NT - 1 : tr);
                uint32_t off = (uint32_t)((buf * KPH + lane) * STROW + 64) * 4u;
                cpAsync4(stU0 + off, emA + (size_t)tr * EMW + 256);
                cpAsync4(stU1 + off, emB + (size_t)tr * EMW + 256);
            }
            cpCommit();
        };

        stageC(0, 1 + (0 - w) * KPH);
        stageC(1, 1 + (1 - w) * KPH);

        // t = 0 init
        float Aa0 = NEGF, Aa1 = NEGF, Aa2 = NEGF, Aa3 = NEGF, Aa4 = NEGF;
        float Ab0 = NEGF, Ab1 = NEGF, Ab2 = NEGF, Ab3 = NEGF, Ab4 = NEGF;
        if (tid == 0) { Aa0 = emA[256]; Aa1 = emA[0]; Ab0 = emB[256]; Ab1 = emB[0]; }
        if (lane == 31) { ringT[(0 * 4 + w) * 32] = Aa3; ringT[(1 * 4 + w) * 32] = Ab3; }
        __syncthreads();

        int buf = 0;
        for (int p = 0; p < NPH_C; p++) {
            int bufN = buf + 2; if (bufN >= 3) bufN -= 3;
            stageC(bufN, 1 + (p + 2 - w) * KPH);
            cpWait2();
            __syncwarp();
            const int tB = 1 + (p - w) * KPH;
            if (p >= w && tB < lenMax) {
                const float* rowA = stage + (0 * 4 + w) * STQ + buf * KPH * STROW;
                const float* rowB = stage + (1 * 4 + w) * STQ + buf * KPH * STROW;
#pragma unroll
                for (int k = 0; k < KPH; k++) {
                    const int t = tB + k;
                    float2 ea = *(const float2*)(rowA + k * STROW + 2 * lane);
                    float eba = rowA[k * STROW + 64];
                    float2 eb = *(const float2*)(rowB + k * STROW + 2 * lane);
                    float ebb = rowB[k * STROW + 64];
                    float n3a = __shfl_up_sync(0xffffffffu, Aa3, 1);
                    float n3b = __shfl_up_sync(0xffffffffu, Ab3, 1);
                    float bna = ringT[(0 * 4 + wp) * 32 + ((t - 1) & 31)];
                    float bnb = ringT[(1 * 4 + wp) * 32 + ((t - 1) & 31)];
                    n3a = (lane == 0) ? ((w == 0) ? NEGF : bna) : n3a;
                    n3b = (lane == 0) ? ((w == 0) ? NEGF : bnb) : n3b;
                    float mn, md, mx;
                    if (t < lenA) {
                        float m0 = fmaxf(Aa0, n3a);
                        float q0 = m0 + __logf(1.f + __expf(fminf(Aa0, n3a) - m0)) + eba;
                        float a3v = s1a ? n3a : NEGF;
                        sort3(Aa1, Aa0, a3v, mn, md, mx);
                        float q1 = mx + __logf(1.f + __expf(mn - mx) + __expf(md - mx)) + ea.x;
                        float m2 = fmaxf(Aa2, Aa1);
                        float q2 = m2 + __logf(1.f + __expf(fminf(Aa2, Aa1) - m2)) + eba;
                        float b3v = s3a ? Aa1 : NEGF;
                        sort3(Aa3, Aa2, b3v, mn, md, mx);
                        float q3 = mx + __logf(1.f + __expf(mn - mx) + __expf(md - mx)) + ea.y;
                        if (w == 3) {
                            float m4 = fmaxf(Aa4, Aa3);
                            float q4 = m4 + __logf(1.f + __expf(fminf(Aa4, Aa3) - m4)) + eba;
                            Aa4 = (lane == 31) ? q4 : Aa4;
                        }
                        if (lane == 31) ringT[(0 * 4 + w) * 32 + (t & 31)] = q3;
                        Aa0 = q0; Aa1 = q1; Aa2 = q2; Aa3 = q3;
                    }
                    if (t < lenB) {
                        float m0 = fmaxf(Ab0, n3b);
                        float q0 = m0 + __logf(1.f + __expf(fminf(Ab0, n3b) - m0)) + ebb;
                        float a3v = s1b ? n3b : NEGF;
                        sort3(Ab1, Ab0, a3v, mn, md, mx);
                        float q1 = mx + __logf(1.f + __expf(mn - mx) + __expf(md - mx)) + eb.x;
                        float m2 = fmaxf(Ab2, Ab1);
                        float q2 = m2 + __logf(1.f + __expf(fminf(Ab2, Ab1) - m2)) + ebb;
                        float b3v = s3b ? Ab1 : NEGF;
                        sort3(Ab3, Ab2, b3v, mn, md, mx);
                        float q3 = mx + __logf(1.f + __expf(mn - mx) + __expf(md - mx)) + eb.y;
                        if (w == 3) {
                            float m4 = fmaxf(Ab4, Ab3);
                            float q4 = m4 + __logf(1.f + __expf(fminf(Ab4, Ab3) - m4)) + ebb;
                            Ab4 = (lane == 31) ? q4 : Ab4;
                        }
                        if (lane == 31) ringT[(1 * 4 + w) * 32 + (t & 31)] = q3;
                        Ab0 = q0; Ab1 = q1; Ab2 = q2; Ab3 = q3;
                    }
                }
            }
            buf++; if (buf >= 3) buf -= 3;
            __syncthreads();
        }

        actc[0 * NL + 4 * tid + 0] = Aa0;
        actc[0 * NL + 4 * tid + 1] = Aa1;
        actc[0 * NL + 4 * tid + 2] = Aa2;
        actc[0 * NL + 4 * tid + 3] = Aa3;
        actc[1 * NL + 4 * tid + 0] = Ab0;
        actc[1 * NL + 4 * tid + 1] = Ab1;
        actc[1 * NL + 4 * tid + 2] = Ab2;
        actc[1 * NL + 4 * tid + 3] = Ab3;
        if (tid == 127) { actc[0 * NL + 512] = Aa4; actc[1 * NL + 512] = Ab4; }
        __syncthreads();
        if (tid < 2) {
            int bb = (tid == 0) ? b0 : b1;
            int tl = tg_len[bb];
            float aL = actc[tid * NL + 2 * tl];
            float aP = actc[tid * NL + 2 * tl - 1];
            float m = fmaxf(aL, aP);
            float ll = m + __logf(__expf(aL - m) + __expf(aP - m));
            g_loss[bb] = -ll / (float)tl;
        }
    }
}

// ----------------------------------------------------------------------------
// Kernel 5: final reduction to scalar
// ----------------------------------------------------------------------------
__global__ void reduce_kernel(float* __restrict__ out) {
    const int tid = threadIdx.x;      // 128
    float v = g_loss[tid];
#pragma unroll
    for (int o = 16; o > 0; o >>= 1) v += __shfl_down_sync(0xffffffffu, v, o);
    __shared__ float ws[4];
    if ((tid & 31) == 0) ws[tid >> 5] = v;
    __syncthreads();
    if (tid == 0) out[0] = (ws[0] + ws[1] + ws[2] + ws[3]) * (1.f / (float)NB);
}

extern "C" void kernel_launch(void* const* d_in, const int* in_sizes, int n_in,
                              void* d_out, int out_size) {
    const float* lp  = (const float*)d_in[0];  // (B,T,V) f32
    const float* fm  = (const float*)d_in[1];  // (V,D)   f32
    const int*   tgt = (const int*)  d_in[2];  // (B,S)   i32
    const int*   il  = (const int*)  d_in[3];  // (B,)    i32
    const int*   tl  = (const int*)  d_in[4];  // (B,)    i32
    float* out = (float*)d_out;

    // dynamic smem: stage 2*4*3*16*68 + bndR 2*4*1312 floats = 146,432 B
    const int dynSmem = (STAGE_FLOATS + 2 * 4 * 1312) * 4;
    cudaFuncSetAttribute(main_kernel, cudaFuncAttributeMaxDynamicSharedMemorySize, dynSmem);

    prep_kernel<<<512, 256>>>(lp, fm);
    em_kernel<<<1024, 256>>>(lp, tgt);
    cost_kernel<<<dim3(16, 64), 256>>>(fm, tgt);
    main_kernel<<<NB, 128, dynSmem>>>(tgt, il, tl);
    reduce_kernel<<<1, 128>>>(out);
}

// round 11
// speedup vs baseline: 1.7460x; 1.7460x over previous
#include <cuda_runtime.h>
#include <cstddef>
#include <cstdint>

#define NB 64
#define NT 1024
#define NV 256
#define NS 256
#define ND 24
#define NL 513          // 2*NS+1
#define DGA 1344        // allocated dg rows per batch
#define EMW 260         // em row: [0..255]=labels, [256]=blank, pad to 260
#define KPH 16          // steps per phase
#define MLAG_S 3        // sdtw inter-warp lag (phases): (m-1)*16 >= 31 -> m=3
#define NPH_S 87        // sdtw phases: 66 active + 3*7 lag
#define NPH_C 71        // ctc phases: 64 active + 7 lag
#define STROW 36        // staged row: 32 data floats (+blank at [32] for ctc), padded
#define STQ (3 * KPH * STROW)   // per-warp stage floats (3 buffers)
#define GAMMA 0.1f
#define NEGF (-1e10f)
#define BIGF (1e10f)

// Scratch (no allocation allowed)
__device__ float g_pred[NB * NT * ND];            // predicted features (B,T,D)
__device__ float g_cost[(size_t)NB * DGA * NS];   // cost, [b][dg][j], dg=i+j+2
__device__ float g_em[(size_t)NB * NT * EMW];     // emissions per label + blank
__device__ float g_loss[2 * NB];                  // [0..63] ctc, [64..127] sdtw

// mn <= md <= mx with pure min/max (no cancellation)
__device__ __forceinline__ void sort3(float a, float b, float c,
                                      float& mn, float& md, float& mx) {
    float t1 = fminf(a, b);
    float t2 = fmaxf(a, b);
    mn = fminf(t1, c);
    mx = fmaxf(t2, c);
    md = fmaxf(t1, fminf(t2, c));
}

__device__ __forceinline__ void cpAsync16(uint32_t dst, const void* src) {
    asm volatile("cp.async.cg.shared.global [%0], [%1], 16;" :: "r"(dst), "l"(src));
}
__device__ __forceinline__ void cpAsync4(uint32_t dst, const void* src) {
    asm volatile("cp.async.ca.shared.global [%0], [%1], 4;" :: "r"(dst), "l"(src));
}
__device__ __forceinline__ void cpCommit() {
    asm volatile("cp.async.commit_group;" ::: "memory");
}
__device__ __forceinline__ void cpWait2() {
    asm volatile("cp.async.wait_group 2;" ::: "memory");
}

// ----------------------------------------------------------------------------
// Kernel 1: pred = exp(log_probs) @ fm   (65536 x 256) @ (256 x 24)
// ----------------------------------------------------------------------------
__global__ __launch_bounds__(256) void prep_kernel(const float* __restrict__ lp,
                                                   const float* __restrict__ fm) {
    __shared__ float eS[64 * 129];
    __shared__ float fmS[64 * 25];

    const int tid = threadIdx.x;
    const int row0 = blockIdx.x * 128;
    const int rg = tid >> 3;
    const int dgrp = tid & 7;

    float acc[4][3];
#pragma unroll
    for (int i = 0; i < 4; i++)
#pragma unroll
        for (int j = 0; j < 3; j++) acc[i][j] = 0.f;

    for (int v0 = 0; v0 < NV; v0 += 64) {
        for (int idx = tid; idx < 64 * 24; idx += 256) {
            int v = idx / 24, d = idx - v * 24;
            fmS[v * 25 + d] = fm[(v0 + v) * ND + d];
        }
        for (int idx = tid; idx < 128 * 64; idx += 256) {
            int r = idx >> 6, v = idx & 63;
            eS[v * 129 + r] = __expf(lp[(size_t)(row0 + r) * NV + v0 + v]);
        }
        __syncthreads();

#pragma unroll 4
        for (int v = 0; v < 64; v++) {
            float e0 = eS[v * 129 + rg * 4 + 0];
            float e1 = eS[v * 129 + rg * 4 + 1];
            float e2 = eS[v * 129 + rg * 4 + 2];
            float e3 = eS[v * 129 + rg * 4 + 3];
            float f0 = fmS[v * 25 + dgrp * 3 + 0];
            float f1 = fmS[v * 25 + dgrp * 3 + 1];
            float f2 = fmS[v * 25 + dgrp * 3 + 2];
            acc[0][0] += e0 * f0; acc[0][1] += e0 * f1; acc[0][2] += e0 * f2;
            acc[1][0] += e1 * f0; acc[1][1] += e1 * f1; acc[1][2] += e1 * f2;
            acc[2][0] += e2 * f0; acc[2][1] += e2 * f1; acc[2][2] += e2 * f2;
            acc[3][0] += e3 * f0; acc[3][1] += e3 * f1; acc[3][2] += e3 * f2;
        }
        __syncthreads();
    }

#pragma unroll
    for (int i = 0; i < 4; i++)
#pragma unroll
        for (int j = 0; j < 3; j++)
            g_pred[(size_t)(row0 + rg * 4 + i) * ND + dgrp * 3 + j] = acc[i][j];
}

// ----------------------------------------------------------------------------
// Kernel 2: sdtw cost matrix, layout [b][dg][j], coalesced via diagonal rotation.
// ----------------------------------------------------------------------------
__global__ __launch_bounds__(256) void cost_kernel(const float* __restrict__ fm,
                                                   const int* __restrict__ targets) {
    __shared__ float predS[64 * 25];
    __shared__ float qS[256 * 25];
    __shared__ float pn[64];
    __shared__ float qn[256];
    __shared__ int qlab[256];

    const int tid = threadIdx.x;
    const int b = blockIdx.y;
    const int i0 = blockIdx.x * 64;

    qlab[tid] = targets[b * NS + tid];
    for (int idx = tid; idx < 64 * 24; idx += 256)
        predS[(idx / 24) * 25 + (idx % 24)] = g_pred[(size_t)(b * NT + i0) * ND + idx];
    __syncthreads();
    for (int idx = tid; idx < 256 * 24; idx += 256) {
        int c = idx / 24, d = idx - c * 24;
        qS[c * 25 + d] = fm[qlab[c] * ND + d];
    }
    __syncthreads();
    if (tid < 64) {
        float s = 0.f;
#pragma unroll
        for (int d = 0; d < ND; d++) { float x = predS[tid * 25 + d]; s += x * x; }
        pn[tid] = s;
    }
    {
        float s = 0.f;
#pragma unroll
        for (int d = 0; d < ND; d++) { float x = qS[tid * 25 + d]; s += x * x; }
        qn[tid] = s;
    }
    __syncthreads();

    const int w = tid >> 5;
    const int lane = tid & 31;
    const int j0 = w * 32;

    float p0[ND], p1[ND];
#pragma unroll
    for (int k = 0; k < ND; k++) {
        p0[k] = predS[lane * 25 + k];
        p1[k] = predS[(lane + 32) * 25 + k];
    }
    const float pn0 = pn[lane], pn1 = pn[lane + 32];
    const size_t cb = (size_t)b * DGA;
    const int D0 = i0 + j0 + 2;

#pragma unroll 4
    for (int c = 0; c < 32; c++) {
        int jc = j0 + ((c - lane) & 31);
        float dot0 = 0.f, dot1 = 0.f;
#pragma unroll
        for (int k = 0; k < ND; k++) {
            float q = qS[jc * 25 + k];
            dot0 += p0[k] * q;
            dot1 += p1[k] * q;
        }
        float qnj = qn[jc];
        int dg0 = D0 + c + ((lane > c) ? 32 : 0);
        g_cost[(cb + dg0) * NS + jc] = pn0 + qnj - 2.f * dot0;
        g_cost[(cb + dg0 + 32) * NS + jc] = pn1 + qnj - 2.f * dot1;
    }
}

// ----------------------------------------------------------------------------
// Kernel 3: emission table em[b][t][j] = lp[t][tgt[j]] (j<256); [256] = blank.
// ----------------------------------------------------------------------------
__global__ __launch_bounds__(256) void em_kernel(const float* __restrict__ lp,
                                                 const int* __restrict__ targets) {
    __shared__ float rowS[4][256];
    __shared__ int tgtS[256];

    const int tid = threadIdx.x;
    const int b = blockIdx.x >> 4;
    const int t0 = (blockIdx.x & 15) << 6;

    tgtS[tid] = targets[b * NS + tid];
    const float* lpb = lp + ((size_t)b * NT + t0) * NV;
    float* emb = g_em + ((size_t)b * NT + t0) * EMW;
    __syncthreads();

    for (int tt = 0; tt < 64; tt += 4) {
#pragma unroll
        for (int r = 0; r < 4; r++)
            rowS[r][tid] = lpb[(size_t)(tt + r) * NV + tid];
        __syncthreads();
#pragma unroll
        for (int r = 0; r < 4; r++)
            emb[(size_t)(tt + r) * EMW + tid] = rowS[r][tgtS[tid]];
        if (tid < 4) emb[(size_t)(tt + tid) * EMW + 256] = rowS[tid][0];
        __syncthreads();
    }
}

// ----------------------------------------------------------------------------
// Kernel 4 (fused DP, 8 warps/block = 2 per SMSP for HW latency hiding):
//   blocks 0..63  -> soft-DTW : 1 col/thread, 8 warps (32-col spans), lag m=3
//   blocks 64..127-> CTC      : 2 states/thread, 8 warps, lag m=1
// cp.async per-warp staging; phase-skewed barriers; rings 64 deep.
// ----------------------------------------------------------------------------
extern __shared__ float smf[];

__global__ __launch_bounds__(256) void main_kernel(const int* __restrict__ targets,
                                                   const int* __restrict__ in_len,
                                                   const int* __restrict__ tg_len) {
    float* stage = smf;                                  // [8][3][KPH][STROW]
    const int tid = threadIdx.x;                         // 0..255
    const int lane = tid & 31;
    const int w = tid >> 5;                              // 0..7
    const int bid = blockIdx.x;

    const uint32_t stageU =
        (uint32_t)__cvta_generic_to_shared(stage) + (uint32_t)(w * STQ) * 4u;
    const int rsel = lane >> 3;            // 0..3 : row sub-group
    const int csel = lane & 7;             // 16B chunk within 128B row

    if (bid < NB) {
        // ======================= soft-DTW =======================
        float* bndR = smf + 8 * STQ;                     // [8][1312]
        const int b = bid;
        const int s0 = 32 * w + 2;                       // warp's first diagonal
        const int jj = tid + 1;                          // column (1-based)
        const int wp = (w == 0) ? 0 : (w - 1);

        for (int idx = tid; idx < 8 * 1312; idx += 256) bndR[idx] = BIGF;

        auto stageS = [&](int buf, int dgStart) {
#pragma unroll
            for (int r = 0; r < 4; r++) {
                int row = 4 * r + rsel;
                int dgr = dgStart + row;
                dgr = (dgr < 0) ? 0 : ((dgr > DGA - 1) ? DGA - 1 : dgr);
                uint32_t off = (uint32_t)((buf * KPH + row) * STROW + csel * 4) * 4u;
                cpAsync16(stageU + off,
                          g_cost + ((size_t)b * DGA + dgr) * NS + 32 * w + csel * 4);
            }
            cpCommit();
        };

        stageS(0, s0 + (0 - MLAG_S * w) * KPH);
        stageS(1, s0 + (1 - MLAG_S * w) * KPH);
        __syncthreads();                                 // bndR init visible

        float Rp = BIGF;
        float r3c = (tid == 0) ? 0.f : BIGF;

        int buf = 0;
        for (int p = 0; p < NPH_S; p++) {
            int bufN = buf + 2; if (bufN >= 3) bufN -= 3;
            stageS(bufN, s0 + (p + 2 - MLAG_S * w) * KPH);
            cpWait2();
            __syncwarp();
            const int prel = p - MLAG_S * w;
            if (prel >= 0 && prel <= 65) {
                const int stB = prel * KPH;
                const float* rowB = stage + w * STQ + buf * KPH * STROW + lane;
#pragma unroll
                for (int k = 0; k < KPH; k++) {
                    const int dg = s0 + stB + k;
                    float c = rowB[k * STROW];
                    float r2 = __shfl_up_sync(0xffffffffu, Rp, 1);
                    float bnd = bndR[wp * 1312 + dg - 1];          // broadcast LDS
                    r2 = (lane == 0) ? ((w == 0) ? BIGF : bnd) : r2;
                    float mn, md, mx;
                    sort3(Rp, r2, r3c, mn, md, mx);
                    float sv = 1.f + __expf((mn - md) * 10.f) + __expf((mn - mx) * 10.f);
                    const int i = dg - jj;
                    float Rn = (i >= 1 && i <= NT) ? (c + mn - GAMMA * __logf(sv)) : BIGF;
                    if (lane == 31) bndR[w * 1312 + dg] = Rn;
                    if (dg == NT + NS && tid == 255) g_loss[NB + b] = Rn;
                    r3c = r2;
                    Rp = Rn;
                }
            }
            buf++; if (buf >= 3) buf -= 3;
            __syncthreads();
        }
    } else {
        // ======================= CTC forward =======================
        float* ringT = smf + 8 * STQ;                    // [8][64]
        float* actc = ringT + 8 * 64;                    // [513]
        const int b = bid - NB;
        const int wp = (w == 0) ? 0 : (w - 1);
        // thread tid owns states 2tid (even/blank-type), 2tid+1 (odd/label tid);
        // tid 255 (w7 lane31) also owns state 512.
        bool skip = false;
        if (tid > 0) skip = (targets[b * NS + tid] != targets[b * NS + tid - 1]);
        const float* em = g_em + (size_t)b * NT * EMW;
        const int len = in_len[b];

        auto stageC = [&](int buf, int tStart) {
#pragma unroll
            for (int r = 0; r < 4; r++) {
                int row = 4 * r + rsel;
                int tr = tStart + row;
                tr = (tr < 0) ? 0 : ((tr > NT - 1) ? NT - 1 : tr);
                uint32_t off = (uint32_t)((buf * KPH + row) * STROW + csel * 4) * 4u;
                cpAsync16(stageU + off, em + (size_t)tr * EMW + 32 * w + csel * 4);
            }
            if (lane < KPH) {                             // blank per row
                int tr = tStart + lane;
                tr = (tr < 0) ? 0 : ((tr > NT - 1) ? NT - 1 : tr);
                cpAsync4(stageU + (uint32_t)((buf * KPH + lane) * STROW + 32) * 4u,
                         em + (size_t)tr * EMW + 256);
            }
            cpCommit();
        };

        stageC(0, 1 + (0 - w) * KPH);
        stageC(1, 1 + (1 - w) * KPH);

        // t = 0 init: state0 = blank emission, state1 = label0 emission
        float A0 = NEGF, A1 = NEGF, A4 = NEGF;
        if (tid == 0) { A0 = em[256]; A1 = em[0]; }
        if (lane == 31) ringT[w * 64] = A1;               // slot t=0
        __syncthreads();

        int buf = 0;
        for (int p = 0; p < NPH_C; p++) {
            int bufN = buf + 2; if (bufN >= 3) bufN -= 3;
            stageC(bufN, 1 + (p + 2 - w) * KPH);
            cpWait2();
            __syncwarp();
            const int tB = 1 + (p - w) * KPH;
            if (p >= w && tB < len) {
                const float* rowB = stage + w * STQ + buf * KPH * STROW;
#pragma unroll
                for (int k = 0; k < KPH; k++) {
                    const int t = tB + k;
                    float e = rowB[k * STROW + lane];
                    float eb = rowB[k * STROW + 32];
                    float pA1 = __shfl_up_sync(0xffffffffu, A1, 1);
                    float bnd = ringT[wp * 64 + ((t - 1) & 63)];   // broadcast LDS
                    pA1 = (lane == 0) ? ((w == 0) ? NEGF : bnd) : pA1;
                    if (t < len) {                                 // uniform per block
                        // even state 2tid: lse(A0, prevA1) + blank
                        float m0 = fmaxf(A0, pA1);
                        float q0 = m0 + __logf(1.f + __expf(fminf(A0, pA1) - m0)) + eb;
                        // odd state 2tid+1: lse(A1, A0, skip?prevA1:NEG) + label
                        float av = skip ? pA1 : NEGF;
                        float mn, md, mx;
                        sort3(A1, A0, av, mn, md, mx);
                        float q1 = mx + __logf(1.f + __expf(mn - mx) + __expf(md - mx)) + e;
                        // state 512 (even): lse(A4, state511=A1 old) + blank — w7 only
                        if (w == 7) {
                            float m4 = fmaxf(A4, A1);
                            float q4 = m4 + __logf(1.f + __expf(fminf(A4, A1) - m4)) + eb;
                            A4 = (lane == 31) ? q4 : A4;
                        }
                        if (lane == 31) ringT[w * 64 + (t & 63)] = q1;
                        A0 = q0; A1 = q1;
                    }
                }
            }
            buf++; if (buf >= 3) buf -= 3;
            __syncthreads();
        }

        actc[2 * tid + 0] = A0;
        actc[2 * tid + 1] = A1;
        if (tid == 255) actc[512] = A4;
        __syncthreads();
        if (tid == 0) {
            int tl = tg_len[b];
            float aL = actc[2 * tl];
            float aP = actc[2 * tl - 1];
            float m = fmaxf(aL, aP);
            float ll = m + __logf(__expf(aL - m) + __expf(aP - m));
            g_loss[b] = -ll / (float)tl;
        }
    }
}

// ----------------------------------------------------------------------------
// Kernel 5: final reduction to scalar
// ----------------------------------------------------------------------------
__global__ void reduce_kernel(float* __restrict__ out) {
    const int tid = threadIdx.x;      // 128
    float v = g_loss[tid];
#pragma unroll
    for (int o = 16; o > 0; o >>= 1) v += __shfl_down_sync(0xffffffffu, v, o);
    __shared__ float ws[4];
    if ((tid & 31) == 0) ws[tid >> 5] = v;
    __syncthreads();
    if (tid == 0) out[0] = (ws[0] + ws[1] + ws[2] + ws[3]) * (1.f / (float)NB);
}

extern "C" void kernel_launch(void* const* d_in, const int* in_sizes, int n_in,
                              void* d_out, int out_size) {
    const float* lp  = (const float*)d_in[0];  // (B,T,V) f32
    const float* fm  = (const float*)d_in[1];  // (V,D)   f32
    const int*   tgt = (const int*)  d_in[2];  // (B,S)   i32
    const int*   il  = (const int*)  d_in[3];  // (B,)    i32
    const int*   tl  = (const int*)  d_in[4];  // (B,)    i32
    float* out = (float*)d_out;

    // dynamic smem: stage 8*3*16*36 + bndR 8*1312 floats = 97,280 B
    const int dynSmem = (8 * STQ + 8 * 1312) * 4;
    cudaFuncSetAttribute(main_kernel, cudaFuncAttributeMaxDynamicSharedMemorySize, dynSmem);

    prep_kernel<<<512, 256>>>(lp, fm);
    em_kernel<<<1024, 256>>>(lp, tgt);
    cost_kernel<<<dim3(16, 64), 256>>>(fm, tgt);
    main_kernel<<<2 * NB, 256, dynSmem>>>(tgt, il, tl);
    reduce_kernel<<<1, 128>>>(out);
}